// round 5
// baseline (speedup 1.0000x reference)
#include <cuda_runtime.h>

#define T_LEN 512
#define BATCH 1024
#define INF   32
#define H     64
#define OUTF  32
#define BPB   8
#define NBLK  (BATCH / BPB)   // 128 CTAs
#define NTHR  512             // 16 warps, 4 per SMSP
#define SH    92              // h row stride; k-chunk kg at offset kg*12 (8 used)
#define PSTR  288             // per-warp partial buffer: 8 kg-rows x 36

typedef unsigned long long ull;

struct __align__(16) Smem {
    float h1[2][BPB][SH];
    float h2[2][BPB][SH];
    float part[16][PSTR];     // [warp][kg*36 + out], out = 8bg+4ib+jj
    float zfc[BPB][H];
};

__device__ __forceinline__ void fma2(ull& acc, ull a, ull b) {
    asm("fma.rn.f32x2 %0, %1, %2, %3;" : "=l"(acc) : "l"(a), "l"(b), "l"(acc));
}
__device__ __forceinline__ float2 unpack2(ull v) {
    float2 r; asm("mov.b64 {%0, %1}, %2;" : "=f"(r.x), "=f"(r.y) : "l"(v)); return r;
}
__device__ __forceinline__ float foldA(ull v) {
    float2 f = unpack2(v); return f.x + f.y;
}
__device__ __forceinline__ float fast_tanh(float x) {
    float cx = fminf(fmaxf(x, -15.f), 15.f);
    float e;
    asm("ex2.approx.f32 %0, %1;" : "=f"(e) : "f"(cx * 2.8853900817779268f));
    float r;
    asm("rcp.approx.f32 %0, %1;" : "=f"(r) : "f"(e + 1.f));
    return (e - 1.f) * r;
}

__global__ void __launch_bounds__(NTHR, 1)
rnn_fused_kernel(const float* __restrict__ x,
                 const float* __restrict__ Wih1, const float* __restrict__ Whh1,
                 const float* __restrict__ bih1, const float* __restrict__ bhh1,
                 const float* __restrict__ Wih2, const float* __restrict__ Whh2,
                 const float* __restrict__ bih2, const float* __restrict__ bhh2,
                 const float* __restrict__ Wfc1, const float* __restrict__ bfc1,
                 const float* __restrict__ Wfc2, const float* __restrict__ bfc2,
                 float* __restrict__ out)
{
    __shared__ Smem s;
    const int tid  = threadIdx.x;
    const int lane = tid & 31;
    const int wrp  = tid >> 5;          // 0..15, owns j4 = 4*wrp .. +4
    const int kg   = lane & 7;          // k-slice 0..7
    const int bg   = (lane >> 3) & 3;   // batch pair -> batches {2bg, 2bg+1}
    const int j4   = wrp * 4;
    const int bq   = 2 * bg;
    const int kx0  = kg * 4;            // x k-slice
    const int kh0  = kg * 8;            // h k-slice

    // ---- weights into registers (k-paired for f32x2) ----
    ull w1[4][2], wh1[4][4], w2r[4][4], wh2[4][4];
#pragma unroll
    for (int u = 0; u < 4; u++) {
        ulonglong2 a = *(const ulonglong2*)&Wih1[(j4 + u) * INF + kx0];
        w1[u][0] = a.x; w1[u][1] = a.y;
        ulonglong2 c0 = *(const ulonglong2*)&Whh1[(j4 + u) * H + kh0];
        ulonglong2 c1 = *(const ulonglong2*)&Whh1[(j4 + u) * H + kh0 + 4];
        wh1[u][0] = c0.x; wh1[u][1] = c0.y; wh1[u][2] = c1.x; wh1[u][3] = c1.y;
        ulonglong2 d0 = *(const ulonglong2*)&Wih2[(j4 + u) * H + kh0];
        ulonglong2 d1 = *(const ulonglong2*)&Wih2[(j4 + u) * H + kh0 + 4];
        w2r[u][0] = d0.x; w2r[u][1] = d0.y; w2r[u][2] = d1.x; w2r[u][3] = d1.y;
        ulonglong2 e0 = *(const ulonglong2*)&Whh2[(j4 + u) * H + kh0];
        ulonglong2 e1 = *(const ulonglong2*)&Whh2[(j4 + u) * H + kh0 + 4];
        wh2[u][0] = e0.x; wh2[u][1] = e0.y; wh2[u][2] = e1.x; wh2[u][3] = e1.y;
    }

    // reduce-output mapping: out = lane -> (b = lane>>2, j = j4 + (lane&3))
    const int rb = lane >> 2;
    const int rj = j4 + (lane & 3);
    const float bA1 = bih1[rj] + bhh1[rj];
    const float bA2 = bih2[rj] + bhh2[rj];
    // h element j stored at (j>>3)*12 + (j&7)
    const int hwi = rb * SH + (wrp >> 1) * 12 + (wrp & 1) * 4 + (lane & 3);

    float* pw = &s.part[wrp][kg * 36 + 8 * bg];     // + 4*ib for float4 writes
    const float* pr = &s.part[wrp][lane];

    const float* xp0 = x + (size_t)(blockIdx.x * BPB + bq) * T_LEN * INF + kx0;

    // zero h state (buffer 0)
    for (int i = tid; i < 2 * BPB * SH; i += NTHR) {
        (&s.h1[0][0][0])[i] = 0.f;
        (&s.h2[0][0][0])[i] = 0.f;
    }
    ulonglong2 xc[2], xn[2];
#pragma unroll
    for (int ib = 0; ib < 2; ib++)
        xc[ib] = *(const ulonglong2*)(xp0 + (size_t)ib * T_LEN * INF);
    __syncthreads();

    int cur = 0;
    for (int t = 0; t < T_LEN; t++) {
        const int nxt = cur ^ 1;
        const int tn = (t + 1 < T_LEN) ? (t + 1) : (T_LEN - 1);
#pragma unroll
        for (int ib = 0; ib < 2; ib++)
            xn[ib] = *(const ulonglong2*)(xp0 + (size_t)ib * T_LEN * INF + (size_t)tn * INF);

        // ---------- layer 1 partials ----------
#pragma unroll
        for (int ib = 0; ib < 2; ib++) {
            const float* hb = &s.h1[cur][bq + ib][kg * 12];
            ulonglong2 h0 = *(const ulonglong2*)hb;
            ulonglong2 h1v = *(const ulonglong2*)(hb + 4);
            const ull xa = xc[ib].x, xb = xc[ib].y;
            ull a0 = 0ull, a1 = 0ull, a2 = 0ull, a3 = 0ull;
            fma2(a0, xa, w1[0][0]); fma2(a1, xa, w1[1][0]);
            fma2(a2, xa, w1[2][0]); fma2(a3, xa, w1[3][0]);
            fma2(a0, xb, w1[0][1]); fma2(a1, xb, w1[1][1]);
            fma2(a2, xb, w1[2][1]); fma2(a3, xb, w1[3][1]);
            fma2(a0, h0.x, wh1[0][0]); fma2(a1, h0.x, wh1[1][0]);
            fma2(a2, h0.x, wh1[2][0]); fma2(a3, h0.x, wh1[3][0]);
            fma2(a0, h0.y, wh1[0][1]); fma2(a1, h0.y, wh1[1][1]);
            fma2(a2, h0.y, wh1[2][1]); fma2(a3, h0.y, wh1[3][1]);
            fma2(a0, h1v.x, wh1[0][2]); fma2(a1, h1v.x, wh1[1][2]);
            fma2(a2, h1v.x, wh1[2][2]); fma2(a3, h1v.x, wh1[3][2]);
            fma2(a0, h1v.y, wh1[0][3]); fma2(a1, h1v.y, wh1[1][3]);
            fma2(a2, h1v.y, wh1[2][3]); fma2(a3, h1v.y, wh1[3][3]);
            float4 v = make_float4(foldA(a0), foldA(a1), foldA(a2), foldA(a3));
            *(float4*)(pw + 4 * ib) = v;
        }
        __syncwarp();
        {   // reduce 8 k-slices -> tanh -> h1[nxt]
            float s0 = pr[0]   + pr[36];
            float s1 = pr[72]  + pr[108];
            float s2 = pr[144] + pr[180];
            float s3 = pr[216] + pr[252];
            (&s.h1[nxt][0][0])[hwi] = fast_tanh(((s0 + s1) + (s2 + s3)) + bA1);
        }
        __syncthreads();

        // ---------- layer 2 partials ----------
#pragma unroll
        for (int ib = 0; ib < 2; ib++) {
            const float* hb1 = &s.h1[nxt][bq + ib][kg * 12];
            const float* hb2 = &s.h2[cur][bq + ib][kg * 12];
            ulonglong2 p0 = *(const ulonglong2*)hb1;
            ulonglong2 p1 = *(const ulonglong2*)(hb1 + 4);
            ulonglong2 q0 = *(const ulonglong2*)hb2;
            ulonglong2 q1 = *(const ulonglong2*)(hb2 + 4);
            ull a0 = 0ull, a1 = 0ull, a2 = 0ull, a3 = 0ull;
            fma2(a0, p0.x, w2r[0][0]); fma2(a1, p0.x, w2r[1][0]);
            fma2(a2, p0.x, w2r[2][0]); fma2(a3, p0.x, w2r[3][0]);
            fma2(a0, p0.y, w2r[0][1]); fma2(a1, p0.y, w2r[1][1]);
            fma2(a2, p0.y, w2r[2][1]); fma2(a3, p0.y, w2r[3][1]);
            fma2(a0, p1.x, w2r[0][2]); fma2(a1, p1.x, w2r[1][2]);
            fma2(a2, p1.x, w2r[2][2]); fma2(a3, p1.x, w2r[3][2]);
            fma2(a0, p1.y, w2r[0][3]); fma2(a1, p1.y, w2r[1][3]);
            fma2(a2, p1.y, w2r[2][3]); fma2(a3, p1.y, w2r[3][3]);
            fma2(a0, q0.x, wh2[0][0]); fma2(a1, q0.x, wh2[1][0]);
            fma2(a2, q0.x, wh2[2][0]); fma2(a3, q0.x, wh2[3][0]);
            fma2(a0, q0.y, wh2[0][1]); fma2(a1, q0.y, wh2[1][1]);
            fma2(a2, q0.y, wh2[2][1]); fma2(a3, q0.y, wh2[3][1]);
            fma2(a0, q1.x, wh2[0][2]); fma2(a1, q1.x, wh2[1][2]);
            fma2(a2, q1.x, wh2[2][2]); fma2(a3, q1.x, wh2[3][2]);
            fma2(a0, q1.y, wh2[0][3]); fma2(a1, q1.y, wh2[1][3]);
            fma2(a2, q1.y, wh2[2][3]); fma2(a3, q1.y, wh2[3][3]);
            float4 v = make_float4(foldA(a0), foldA(a1), foldA(a2), foldA(a3));
            *(float4*)(pw + 4 * ib) = v;
        }
        __syncwarp();
        {
            float s0 = pr[0]   + pr[36];
            float s1 = pr[72]  + pr[108];
            float s2 = pr[144] + pr[180];
            float s3 = pr[216] + pr[252];
            (&s.h2[nxt][0][0])[hwi] = fast_tanh(((s0 + s1) + (s2 + s3)) + bA2);
        }
        xc[0] = xn[0]; xc[1] = xn[1];
        __syncthreads();
        cur = nxt;
    }

    // ---------- FC head ----------
    {
        const int j = tid & 63;
        const int b = tid >> 6;       // 0..7
        float acc = bfc1[j];
#pragma unroll
        for (int c = 0; c < 8; c++) {
            const float* hb = &s.h2[cur][b][c * 12];
            const float* wr = &Wfc1[j * H + c * 8];
#pragma unroll
            for (int u = 0; u < 8; u++) acc = fmaf(hb[u], wr[u], acc);
        }
        s.zfc[b][j] = fmaxf(acc, 0.f);
    }
    __syncthreads();
    if (tid < BPB * OUTF) {
        const int b = tid >> 5;
        const int o = tid & 31;
        float r = bfc2[o];
#pragma unroll
        for (int k = 0; k < H; k++) r = fmaf(s.zfc[b][k], Wfc2[o * H + k], r);
        out[(blockIdx.x * BPB + b) * OUTF + o] = r;
    }
}

extern "C" void kernel_launch(void* const* d_in, const int* in_sizes, int n_in,
                              void* d_out, int out_size)
{
    (void)in_sizes; (void)n_in; (void)out_size;
    const float* x    = (const float*)d_in[0];
    const float* Wih1 = (const float*)d_in[1];
    const float* Whh1 = (const float*)d_in[2];
    const float* bih1 = (const float*)d_in[3];
    const float* bhh1 = (const float*)d_in[4];
    const float* Wih2 = (const float*)d_in[5];
    const float* Whh2 = (const float*)d_in[6];
    const float* bih2 = (const float*)d_in[7];
    const float* bhh2 = (const float*)d_in[8];
    const float* Wfc1 = (const float*)d_in[9];
    const float* bfc1 = (const float*)d_in[10];
    const float* Wfc2 = (const float*)d_in[11];
    const float* bfc2 = (const float*)d_in[12];
    float* out = (float*)d_out;

    rnn_fused_kernel<<<NBLK, NTHR>>>(x, Wih1, Whh1, bih1, bhh1,
                                     Wih2, Whh2, bih2, bhh2,
                                     Wfc1, bfc1, Wfc2, bfc2, out);
}

// round 6
// speedup vs baseline: 1.3612x; 1.3612x over previous
#include <cuda_runtime.h>

#define T_LEN 512
#define INF   32
#define H     64
#define OUTF  32
#define BPB   8
#define NBLK  128
#define NTHR  256
#define SH    92              // h row stride; j stored at (j>>3)*12 + (j&7)
#define SPB   84
#define PWRP  672             // 8*SPB

typedef unsigned long long ull;

struct __align__(16) Smem {
    float h1[2][BPB][SH];
    float h2[2][BPB][SH];
    float part1[8][PWRP];    // layer2 partials
    float part2[8][PWRP];    // layer1 partials
    float zfc[BPB][H];
};

__device__ __forceinline__ void fma2(ull& acc, ull a, ull b) {
    asm("fma.rn.f32x2 %0, %1, %2, %3;" : "=l"(acc) : "l"(a), "l"(b), "l"(acc));
}
__device__ __forceinline__ ull add2(ull a, ull b) {
    ull r; asm("add.rn.f32x2 %0, %1, %2;" : "=l"(r) : "l"(a), "l"(b)); return r;
}
__device__ __forceinline__ float2 unpack2(ull v) {
    float2 r; asm("mov.b64 {%0, %1}, %2;" : "=f"(r.x), "=f"(r.y) : "l"(v)); return r;
}
__device__ __forceinline__ float foldA(ull v) {
    float2 f = unpack2(v); return f.x + f.y;
}
__device__ __forceinline__ float fast_tanh(float x) {
    float cx = fminf(fmaxf(x, -15.f), 15.f);
    float e;
    asm("ex2.approx.f32 %0, %1;" : "=f"(e) : "f"(cx * 2.8853900817779268f));
    float r;
    asm("rcp.approx.f32 %0, %1;" : "=f"(r) : "f"(e + 1.f));
    return (e - 1.f) * r;
}

__global__ void __launch_bounds__(NTHR, 1)
rnn_fused_kernel(const float* __restrict__ x,
                 const float* __restrict__ Wih1, const float* __restrict__ Whh1,
                 const float* __restrict__ bih1, const float* __restrict__ bhh1,
                 const float* __restrict__ Wih2, const float* __restrict__ Whh2,
                 const float* __restrict__ bih2, const float* __restrict__ bhh2,
                 const float* __restrict__ Wfc1, const float* __restrict__ bfc1,
                 const float* __restrict__ Wfc2, const float* __restrict__ bfc2,
                 float* __restrict__ out)
{
    extern __shared__ float smem_raw[];
    Smem* s = reinterpret_cast<Smem*>(smem_raw);
    const int tid   = threadIdx.x;
    const int kg    = tid & 7;
    const int bg2   = (tid >> 3) & 1;
    const int jg    = tid >> 4;
    const int wrp   = tid >> 5;
    const int jglow = jg & 1;
    const int lane  = tid & 31;
    const int j4  = jg * 4;
    const int bq  = bg2 * 4;
    const int kx0 = kg * 4;
    const int kh0 = kg * 8;

    // ---- weights into registers (k-paired for f32x2) ----
    ull w1[4][2], wh1[4][4], w2r[4][4], wh2[4][4];
#pragma unroll
    for (int u = 0; u < 4; u++) {
        ulonglong2 a = *(const ulonglong2*)&Wih1[(j4 + u) * INF + kx0];
        w1[u][0] = a.x; w1[u][1] = a.y;
        ulonglong2 c0 = *(const ulonglong2*)&Whh1[(j4 + u) * H + kh0];
        ulonglong2 c1 = *(const ulonglong2*)&Whh1[(j4 + u) * H + kh0 + 4];
        wh1[u][0] = c0.x; wh1[u][1] = c0.y; wh1[u][2] = c1.x; wh1[u][3] = c1.y;
        ulonglong2 d0 = *(const ulonglong2*)&Wih2[(j4 + u) * H + kh0];
        ulonglong2 d1 = *(const ulonglong2*)&Wih2[(j4 + u) * H + kh0 + 4];
        w2r[u][0] = d0.x; w2r[u][1] = d0.y; w2r[u][2] = d1.x; w2r[u][3] = d1.y;
        ulonglong2 e0 = *(const ulonglong2*)&Whh2[(j4 + u) * H + kh0];
        ulonglong2 e1 = *(const ulonglong2*)&Whh2[(j4 + u) * H + kh0 + 4];
        wh2[u][0] = e0.x; wh2[u][1] = e0.y; wh2[u][2] = e1.x; wh2[u][3] = e1.y;
    }

    const int jf = wrp * 8 + (lane & 7);
    const float bA1 = bih1[jf] + bhh1[jf];
    const float bA2 = bih2[jf] + bhh2[jf];
    const int hw0 = (lane >> 3) * SH + wrp * 12 + (lane & 7);
    const int hw1 = hw0 + 4 * SH;

    float* pw1 = &s->part1[wrp][bq * SPB + jglow * 40 + kg];
    float* pw2 = &s->part2[wrp][bq * SPB + jglow * 40 + kg];
    const float* pr1 = &s->part1[wrp][(lane >> 3) * SPB + (lane & 7) * 10];
    const float* pr2 = &s->part2[wrp][(lane >> 3) * SPB + (lane & 7) * 10];

    const float* xp0 = x + (size_t)(blockIdx.x * BPB + bq) * T_LEN * INF + kx0;

    // zero h state
    for (int i = tid; i < 2 * BPB * SH; i += NTHR) {
        (&s->h1[0][0][0])[i] = 0.f;
        (&s->h2[0][0][0])[i] = 0.f;
    }
    ulonglong2 xc[4], xn[4];
#pragma unroll
    for (int ib = 0; ib < 4; ib++)
        xc[ib] = *(const ulonglong2*)(xp0 + (size_t)ib * T_LEN * INF);
    __syncthreads();

    // ---------- preamble: h1(0) = tanh(x(0)@W1^T + b1)  (h1 state is 0) ----------
#pragma unroll
    for (int ib = 0; ib < 4; ib++) {
        ull c0 = 0ull, c1 = 0ull, c2 = 0ull, c3 = 0ull;
        const ull xa = xc[ib].x, xb = xc[ib].y;
        fma2(c0, xa, w1[0][0]); fma2(c1, xa, w1[1][0]);
        fma2(c2, xa, w1[2][0]); fma2(c3, xa, w1[3][0]);
        fma2(c0, xb, w1[0][1]); fma2(c1, xb, w1[1][1]);
        fma2(c2, xb, w1[2][1]); fma2(c3, xb, w1[3][1]);
        pw2[ib * SPB +  0] = foldA(c0);
        pw2[ib * SPB + 10] = foldA(c1);
        pw2[ib * SPB + 20] = foldA(c2);
        pw2[ib * SPB + 30] = foldA(c3);
    }
    __syncwarp();
    {
        ull p0 = *(const ull*)(pr2);
        ull p1 = *(const ull*)(pr2 + 2);
        ull p2 = *(const ull*)(pr2 + 4);
        ull p3 = *(const ull*)(pr2 + 6);
        ull q0 = *(const ull*)(pr2 + 4 * SPB);
        ull q1 = *(const ull*)(pr2 + 4 * SPB + 2);
        ull q2 = *(const ull*)(pr2 + 4 * SPB + 4);
        ull q3 = *(const ull*)(pr2 + 4 * SPB + 6);
        float2 f0 = unpack2(add2(add2(p0, p1), add2(p2, p3)));
        float2 f1 = unpack2(add2(add2(q0, q1), add2(q2, q3)));
        (&s->h1[1][0][0])[hw0] = fast_tanh(f0.x + f0.y + bA1);
        (&s->h1[1][0][0])[hw1] = fast_tanh(f1.x + f1.y + bA1);
    }
#pragma unroll
    for (int ib = 0; ib < 4; ib++)
        xc[ib] = *(const ulonglong2*)(xp0 + (size_t)ib * T_LEN * INF + INF);  // x(1)
    __syncthreads();

    // ---------- main loop: one barrier per step ----------
    int cur = 0;
    for (int t = 0; t < T_LEN; t++) {
        const int nxt = cur ^ 1;
        const int tn = (t + 2 < T_LEN) ? (t + 2) : (T_LEN - 1);
#pragma unroll
        for (int ib = 0; ib < 4; ib++)
            xn[ib] = *(const ulonglong2*)(xp0 + (size_t)ib * T_LEN * INF + (size_t)tn * INF);

#pragma unroll
        for (int ib = 0; ib < 4; ib++) {
            const float* hb1 = &s->h1[nxt][bq + ib][kg * 12];   // h1(t)
            const float* hb2 = &s->h2[cur][bq + ib][kg * 12];   // h2(t-1)
            ulonglong2 p0 = *(const ulonglong2*)hb1;
            ulonglong2 p1 = *(const ulonglong2*)(hb1 + 4);
            ulonglong2 q0 = *(const ulonglong2*)hb2;
            ulonglong2 q1 = *(const ulonglong2*)(hb2 + 4);

            // layer2(t): h1(t)@W2^T + h2(t-1)@Wh2^T
            ull a0 = 0ull, a1 = 0ull, a2 = 0ull, a3 = 0ull;
            fma2(a0, p0.x, w2r[0][0]); fma2(a1, p0.x, w2r[1][0]);
            fma2(a2, p0.x, w2r[2][0]); fma2(a3, p0.x, w2r[3][0]);
            fma2(a0, p0.y, w2r[0][1]); fma2(a1, p0.y, w2r[1][1]);
            fma2(a2, p0.y, w2r[2][1]); fma2(a3, p0.y, w2r[3][1]);
            fma2(a0, p1.x, w2r[0][2]); fma2(a1, p1.x, w2r[1][2]);
            fma2(a2, p1.x, w2r[2][2]); fma2(a3, p1.x, w2r[3][2]);
            fma2(a0, p1.y, w2r[0][3]); fma2(a1, p1.y, w2r[1][3]);
            fma2(a2, p1.y, w2r[2][3]); fma2(a3, p1.y, w2r[3][3]);
            fma2(a0, q0.x, wh2[0][0]); fma2(a1, q0.x, wh2[1][0]);
            fma2(a2, q0.x, wh2[2][0]); fma2(a3, q0.x, wh2[3][0]);
            fma2(a0, q0.y, wh2[0][1]); fma2(a1, q0.y, wh2[1][1]);
            fma2(a2, q0.y, wh2[2][1]); fma2(a3, q0.y, wh2[3][1]);
            fma2(a0, q1.x, wh2[0][2]); fma2(a1, q1.x, wh2[1][2]);
            fma2(a2, q1.x, wh2[2][2]); fma2(a3, q1.x, wh2[3][2]);
            fma2(a0, q1.y, wh2[0][3]); fma2(a1, q1.y, wh2[1][3]);
            fma2(a2, q1.y, wh2[2][3]); fma2(a3, q1.y, wh2[3][3]);
            pw1[ib * SPB +  0] = foldA(a0);
            pw1[ib * SPB + 10] = foldA(a1);
            pw1[ib * SPB + 20] = foldA(a2);
            pw1[ib * SPB + 30] = foldA(a3);

            // layer1(t+1): x(t+1)@W1^T + h1(t)@Wh1^T   (reuses p0/p1)
            ull c0 = 0ull, c1 = 0ull, c2 = 0ull, c3 = 0ull;
            const ull xa = xc[ib].x, xb = xc[ib].y;
            fma2(c0, xa, w1[0][0]); fma2(c1, xa, w1[1][0]);
            fma2(c2, xa, w1[2][0]); fma2(c3, xa, w1[3][0]);
            fma2(c0, xb, w1[0][1]); fma2(c1, xb, w1[1][1]);
            fma2(c2, xb, w1[2][1]); fma2(c3, xb, w1[3][1]);
            fma2(c0, p0.x, wh1[0][0]); fma2(c1, p0.x, wh1[1][0]);
            fma2(c2, p0.x, wh1[2][0]); fma2(c3, p0.x, wh1[3][0]);
            fma2(c0, p0.y, wh1[0][1]); fma2(c1, p0.y, wh1[1][1]);
            fma2(c2, p0.y, wh1[2][1]); fma2(c3, p0.y, wh1[3][1]);
            fma2(c0, p1.x, wh1[0][2]); fma2(c1, p1.x, wh1[1][2]);
            fma2(c2, p1.x, wh1[2][2]); fma2(c3, p1.x, wh1[3][2]);
            fma2(c0, p1.y, wh1[0][3]); fma2(c1, p1.y, wh1[1][3]);
            fma2(c2, p1.y, wh1[2][3]); fma2(c3, p1.y, wh1[3][3]);
            pw2[ib * SPB +  0] = foldA(c0);
            pw2[ib * SPB + 10] = foldA(c1);
            pw2[ib * SPB + 20] = foldA(c2);
            pw2[ib * SPB + 30] = foldA(c3);
        }
        __syncwarp();
        {   // reduce layer2 -> h2(t) into h2[nxt]
            ull p0 = *(const ull*)(pr1);
            ull p1 = *(const ull*)(pr1 + 2);
            ull p2 = *(const ull*)(pr1 + 4);
            ull p3 = *(const ull*)(pr1 + 6);
            ull q0 = *(const ull*)(pr1 + 4 * SPB);
            ull q1 = *(const ull*)(pr1 + 4 * SPB + 2);
            ull q2 = *(const ull*)(pr1 + 4 * SPB + 4);
            ull q3 = *(const ull*)(pr1 + 4 * SPB + 6);
            float2 f0 = unpack2(add2(add2(p0, p1), add2(p2, p3)));
            float2 f1 = unpack2(add2(add2(q0, q1), add2(q2, q3)));
            (&s->h2[nxt][0][0])[hw0] = fast_tanh(f0.x + f0.y + bA2);
            (&s->h2[nxt][0][0])[hw1] = fast_tanh(f1.x + f1.y + bA2);
        }
        {   // reduce layer1 -> h1(t+1) into h1[cur]
            ull p0 = *(const ull*)(pr2);
            ull p1 = *(const ull*)(pr2 + 2);
            ull p2 = *(const ull*)(pr2 + 4);
            ull p3 = *(const ull*)(pr2 + 6);
            ull q0 = *(const ull*)(pr2 + 4 * SPB);
            ull q1 = *(const ull*)(pr2 + 4 * SPB + 2);
            ull q2 = *(const ull*)(pr2 + 4 * SPB + 4);
            ull q3 = *(const ull*)(pr2 + 4 * SPB + 6);
            float2 f0 = unpack2(add2(add2(p0, p1), add2(p2, p3)));
            float2 f1 = unpack2(add2(add2(q0, q1), add2(q2, q3)));
            (&s->h1[cur][0][0])[hw0] = fast_tanh(f0.x + f0.y + bA1);
            (&s->h1[cur][0][0])[hw1] = fast_tanh(f1.x + f1.y + bA1);
        }
#pragma unroll
        for (int ib = 0; ib < 4; ib++) xc[ib] = xn[ib];
        __syncthreads();
        cur = nxt;
    }
    // T_LEN even -> final h2 is in h2[0]

    // ---------- FC head ----------
    {
        const int j = tid & 63;
        const int brow = tid >> 6;      // 0..3
#pragma unroll
        for (int rep = 0; rep < 2; rep++) {
            const int b = brow + rep * 4;
            float acc = bfc1[j];
#pragma unroll
            for (int c = 0; c < 8; c++) {
                const float* hb = &s->h2[0][b][c * 12];
                const float* wr = &Wfc1[j * H + c * 8];
#pragma unroll
                for (int u = 0; u < 8; u++) acc = fmaf(hb[u], wr[u], acc);
            }
            s->zfc[b][j] = fmaxf(acc, 0.f);
        }
    }
    __syncthreads();
    {
        const int b = tid >> 5;
        const int o = tid & 31;
        float r = bfc2[o];
#pragma unroll
        for (int k = 0; k < H; k++) r = fmaf(s->zfc[b][k], Wfc2[o * H + k], r);
        out[(blockIdx.x * BPB + b) * OUTF + o] = r;
    }
}

extern "C" void kernel_launch(void* const* d_in, const int* in_sizes, int n_in,
                              void* d_out, int out_size)
{
    (void)in_sizes; (void)n_in; (void)out_size;
    const float* x    = (const float*)d_in[0];
    const float* Wih1 = (const float*)d_in[1];
    const float* Whh1 = (const float*)d_in[2];
    const float* bih1 = (const float*)d_in[3];
    const float* bhh1 = (const float*)d_in[4];
    const float* Wih2 = (const float*)d_in[5];
    const float* Whh2 = (const float*)d_in[6];
    const float* bih2 = (const float*)d_in[7];
    const float* bhh2 = (const float*)d_in[8];
    const float* Wfc1 = (const float*)d_in[9];
    const float* bfc1 = (const float*)d_in[10];
    const float* Wfc2 = (const float*)d_in[11];
    const float* bfc2 = (const float*)d_in[12];
    float* out = (float*)d_out;

    size_t smem = sizeof(Smem);
    cudaFuncSetAttribute(rnn_fused_kernel,
                         cudaFuncAttributeMaxDynamicSharedMemorySize, (int)smem);
    rnn_fused_kernel<<<NBLK, NTHR, smem>>>(x, Wih1, Whh1, bih1, bhh1,
                                           Wih2, Whh2, bih2, bhh2,
                                           Wfc1, bfc1, Wfc2, bfc2, out);
}

// round 7
// speedup vs baseline: 1.4395x; 1.0575x over previous
#include <cuda_runtime.h>

#define T_LEN 512
#define INF   32
#define H     64
#define OUTF  32
#define BPB   8
#define NBLK  128
#define NTHR  256             // 8 warps: warps 0-3 = group 0, 4-7 = group 1
#define SH    92              // h row stride; j stored at (j>>3)*12 + (j&7)
#define BSTR  176             // partial-buffer batch stride (mod 32 = 16)
#define PWRP  (4 * BSTR)      // 704 floats per warp

typedef unsigned long long ull;

struct __align__(16) Smem {
    float h1[2][BPB][SH];
    float h2[2][BPB][SH];
    float part1[8][PWRP];     // layer2 partials
    float part2[8][PWRP];     // layer1 partials
    float zfc[BPB][H];
};

#define GBAR(g) asm volatile("bar.sync %0, 128;" :: "r"((g) + 1) : "memory")

__device__ __forceinline__ void fma2(ull& acc, ull a, ull b) {
    asm("fma.rn.f32x2 %0, %1, %2, %3;" : "=l"(acc) : "l"(a), "l"(b), "l"(acc));
}
__device__ __forceinline__ ull add2(ull a, ull b) {
    ull r; asm("add.rn.f32x2 %0, %1, %2;" : "=l"(r) : "l"(a), "l"(b)); return r;
}
__device__ __forceinline__ float2 unpack2(ull v) {
    float2 r; asm("mov.b64 {%0, %1}, %2;" : "=f"(r.x), "=f"(r.y) : "l"(v)); return r;
}
__device__ __forceinline__ float foldA(ull v) {
    float2 f = unpack2(v); return f.x + f.y;
}
__device__ __forceinline__ float red8(const float* pr) {
    ull p0 = *(const ull*)(pr);
    ull p1 = *(const ull*)(pr + 2);
    ull p2 = *(const ull*)(pr + 4);
    ull p3 = *(const ull*)(pr + 6);
    float2 f = unpack2(add2(add2(p0, p1), add2(p2, p3)));
    return f.x + f.y;
}
__device__ __forceinline__ float fast_tanh(float x) {
    float cx = fminf(fmaxf(x, -15.f), 15.f);
    float e;
    asm("ex2.approx.f32 %0, %1;" : "=f"(e) : "f"(cx * 2.8853900817779268f));
    float r;
    asm("rcp.approx.f32 %0, %1;" : "=f"(r) : "f"(e + 1.f));
    return (e - 1.f) * r;
}

__global__ void __launch_bounds__(NTHR, 1)
rnn_fused_kernel(const float* __restrict__ x,
                 const float* __restrict__ Wih1, const float* __restrict__ Whh1,
                 const float* __restrict__ bih1, const float* __restrict__ bhh1,
                 const float* __restrict__ Wih2, const float* __restrict__ Whh2,
                 const float* __restrict__ bih2, const float* __restrict__ bhh2,
                 const float* __restrict__ Wfc1, const float* __restrict__ bfc1,
                 const float* __restrict__ Wfc2, const float* __restrict__ bfc2,
                 float* __restrict__ out)
{
    extern __shared__ float smem_raw[];
    Smem* s = reinterpret_cast<Smem*>(smem_raw);
    const int tid  = threadIdx.x;
    const int lane = tid & 31;
    const int wrp  = tid >> 5;
    const int grp  = wrp >> 2;          // independent group 0/1
    const int wig  = wrp & 3;           // warp-in-group: owns 16 j's
    const int kg   = lane & 7;          // k-slice 0..7
    const int jgl  = lane >> 3;         // j-subgroup 0..3
    const int j4   = wig * 16 + jgl * 4;
    const int bq   = grp * 4;           // group's batch base
    const int kx0  = kg * 4;
    const int kh0  = kg * 8;

    // ---- weights into registers (k-paired for f32x2) ----
    ull w1[4][2], wh1[4][4], w2r[4][4], wh2[4][4];
#pragma unroll
    for (int u = 0; u < 4; u++) {
        ulonglong2 a = *(const ulonglong2*)&Wih1[(j4 + u) * INF + kx0];
        w1[u][0] = a.x; w1[u][1] = a.y;
        ulonglong2 c0 = *(const ulonglong2*)&Whh1[(j4 + u) * H + kh0];
        ulonglong2 c1 = *(const ulonglong2*)&Whh1[(j4 + u) * H + kh0 + 4];
        wh1[u][0] = c0.x; wh1[u][1] = c0.y; wh1[u][2] = c1.x; wh1[u][3] = c1.y;
        ulonglong2 d0 = *(const ulonglong2*)&Wih2[(j4 + u) * H + kh0];
        ulonglong2 d1 = *(const ulonglong2*)&Wih2[(j4 + u) * H + kh0 + 4];
        w2r[u][0] = d0.x; w2r[u][1] = d0.y; w2r[u][2] = d1.x; w2r[u][3] = d1.y;
        ulonglong2 e0 = *(const ulonglong2*)&Whh2[(j4 + u) * H + kh0];
        ulonglong2 e1 = *(const ulonglong2*)&Whh2[(j4 + u) * H + kh0 + 4];
        wh2[u][0] = e0.x; wh2[u][1] = e0.y; wh2[u][2] = e1.x; wh2[u][3] = e1.y;
    }

    // reduce-side mapping: lane handles outputs (b = bloc, j = jo0) and (b, jo1)
    const int bloc = lane >> 3;         // 0..3 within group
    const int jj0  = lane & 7;
    const int jo0  = wig * 16 + jj0;
    const int jo1  = jo0 + 8;
    const float bA1_0 = bih1[jo0] + bhh1[jo0];
    const float bA1_1 = bih1[jo1] + bhh1[jo1];
    const float bA2_0 = bih2[jo0] + bhh2[jo0];
    const float bA2_1 = bih2[jo1] + bhh2[jo1];
    const int hw0 = (bq + bloc) * SH + wig * 24 + jj0;
    const int hw1 = hw0 + 12;

    float* pw1 = &s->part1[wrp][jgl * 40 + kg];
    float* pw2 = &s->part2[wrp][jgl * 40 + kg];
    const float* pr1 = &s->part1[wrp][bloc * BSTR + jj0 * 10];
    const float* pr2 = &s->part2[wrp][bloc * BSTR + jj0 * 10];

    const float* xp0 = x + (size_t)(blockIdx.x * BPB + bq) * T_LEN * INF + kx0;

    // zero h state
    for (int i = tid; i < 2 * BPB * SH; i += NTHR) {
        (&s->h1[0][0][0])[i] = 0.f;
        (&s->h2[0][0][0])[i] = 0.f;
    }
    ulonglong2 xc[4], xn[4];
#pragma unroll
    for (int ib = 0; ib < 4; ib++)
        xc[ib] = *(const ulonglong2*)(xp0 + (size_t)ib * T_LEN * INF);
    __syncthreads();

    // ---------- preamble: h1(0) = tanh(x(0)@W1^T + b1) ----------
#pragma unroll
    for (int ib = 0; ib < 4; ib++) {
        ull c0 = 0ull, c1 = 0ull, c2 = 0ull, c3 = 0ull;
        const ull xa = xc[ib].x, xb = xc[ib].y;
        fma2(c0, xa, w1[0][0]); fma2(c1, xa, w1[1][0]);
        fma2(c2, xa, w1[2][0]); fma2(c3, xa, w1[3][0]);
        fma2(c0, xb, w1[0][1]); fma2(c1, xb, w1[1][1]);
        fma2(c2, xb, w1[2][1]); fma2(c3, xb, w1[3][1]);
        pw2[ib * BSTR +  0] = foldA(c0);
        pw2[ib * BSTR + 10] = foldA(c1);
        pw2[ib * BSTR + 20] = foldA(c2);
        pw2[ib * BSTR + 30] = foldA(c3);
    }
    __syncwarp();
    (&s->h1[1][0][0])[hw0] = fast_tanh(red8(pr2) + bA1_0);
    (&s->h1[1][0][0])[hw1] = fast_tanh(red8(pr2 + 80) + bA1_1);
#pragma unroll
    for (int ib = 0; ib < 4; ib++)
        xc[ib] = *(const ulonglong2*)(xp0 + (size_t)ib * T_LEN * INF + INF);  // x(1)
    GBAR(grp);

    // ---------- main loop: one group-local barrier per step ----------
    int cur = 0;
    for (int t = 0; t < T_LEN; t++) {
        const int nxt = cur ^ 1;
        const int tn = (t + 2 < T_LEN) ? (t + 2) : (T_LEN - 1);
#pragma unroll
        for (int ib = 0; ib < 4; ib++)
            xn[ib] = *(const ulonglong2*)(xp0 + (size_t)ib * T_LEN * INF + (size_t)tn * INF);

#pragma unroll
        for (int ib = 0; ib < 4; ib++) {
            const float* hb1 = &s->h1[nxt][bq + ib][kg * 12];   // h1(t)
            const float* hb2 = &s->h2[cur][bq + ib][kg * 12];   // h2(t-1)
            ulonglong2 p0 = *(const ulonglong2*)hb1;
            ulonglong2 p1 = *(const ulonglong2*)(hb1 + 4);
            ulonglong2 q0 = *(const ulonglong2*)hb2;
            ulonglong2 q1 = *(const ulonglong2*)(hb2 + 4);

            // layer2(t): h1(t)@W2^T + h2(t-1)@Wh2^T
            ull a0 = 0ull, a1 = 0ull, a2 = 0ull, a3 = 0ull;
            fma2(a0, p0.x, w2r[0][0]); fma2(a1, p0.x, w2r[1][0]);
            fma2(a2, p0.x, w2r[2][0]); fma2(a3, p0.x, w2r[3][0]);
            fma2(a0, p0.y, w2r[0][1]); fma2(a1, p0.y, w2r[1][1]);
            fma2(a2, p0.y, w2r[2][1]); fma2(a3, p0.y, w2r[3][1]);
            fma2(a0, p1.x, w2r[0][2]); fma2(a1, p1.x, w2r[1][2]);
            fma2(a2, p1.x, w2r[2][2]); fma2(a3, p1.x, w2r[3][2]);
            fma2(a0, p1.y, w2r[0][3]); fma2(a1, p1.y, w2r[1][3]);
            fma2(a2, p1.y, w2r[2][3]); fma2(a3, p1.y, w2r[3][3]);
            fma2(a0, q0.x, wh2[0][0]); fma2(a1, q0.x, wh2[1][0]);
            fma2(a2, q0.x, wh2[2][0]); fma2(a3, q0.x, wh2[3][0]);
            fma2(a0, q0.y, wh2[0][1]); fma2(a1, q0.y, wh2[1][1]);
            fma2(a2, q0.y, wh2[2][1]); fma2(a3, q0.y, wh2[3][1]);
            fma2(a0, q1.x, wh2[0][2]); fma2(a1, q1.x, wh2[1][2]);
            fma2(a2, q1.x, wh2[2][2]); fma2(a3, q1.x, wh2[3][2]);
            fma2(a0, q1.y, wh2[0][3]); fma2(a1, q1.y, wh2[1][3]);
            fma2(a2, q1.y, wh2[2][3]); fma2(a3, q1.y, wh2[3][3]);
            pw1[ib * BSTR +  0] = foldA(a0);
            pw1[ib * BSTR + 10] = foldA(a1);
            pw1[ib * BSTR + 20] = foldA(a2);
            pw1[ib * BSTR + 30] = foldA(a3);

            // layer1(t+1): x(t+1)@W1^T + h1(t)@Wh1^T   (reuses p0/p1)
            ull c0 = 0ull, c1 = 0ull, c2 = 0ull, c3 = 0ull;
            const ull xa = xc[ib].x, xb = xc[ib].y;
            fma2(c0, xa, w1[0][0]); fma2(c1, xa, w1[1][0]);
            fma2(c2, xa, w1[2][0]); fma2(c3, xa, w1[3][0]);
            fma2(c0, xb, w1[0][1]); fma2(c1, xb, w1[1][1]);
            fma2(c2, xb, w1[2][1]); fma2(c3, xb, w1[3][1]);
            fma2(c0, p0.x, wh1[0][0]); fma2(c1, p0.x, wh1[1][0]);
            fma2(c2, p0.x, wh1[2][0]); fma2(c3, p0.x, wh1[3][0]);
            fma2(c0, p0.y, wh1[0][1]); fma2(c1, p0.y, wh1[1][1]);
            fma2(c2, p0.y, wh1[2][1]); fma2(c3, p0.y, wh1[3][1]);
            fma2(c0, p1.x, wh1[0][2]); fma2(c1, p1.x, wh1[1][2]);
            fma2(c2, p1.x, wh1[2][2]); fma2(c3, p1.x, wh1[3][2]);
            fma2(c0, p1.y, wh1[0][3]); fma2(c1, p1.y, wh1[1][3]);
            fma2(c2, p1.y, wh1[2][3]); fma2(c3, p1.y, wh1[3][3]);
            pw2[ib * BSTR +  0] = foldA(c0);
            pw2[ib * BSTR + 10] = foldA(c1);
            pw2[ib * BSTR + 20] = foldA(c2);
            pw2[ib * BSTR + 30] = foldA(c3);
        }
        __syncwarp();
        // reduce layer2 -> h2(t) into h2[nxt]
        (&s->h2[nxt][0][0])[hw0] = fast_tanh(red8(pr1) + bA2_0);
        (&s->h2[nxt][0][0])[hw1] = fast_tanh(red8(pr1 + 80) + bA2_1);
        // reduce layer1 -> h1(t+1) into h1[cur]
        (&s->h1[cur][0][0])[hw0] = fast_tanh(red8(pr2) + bA1_0);
        (&s->h1[cur][0][0])[hw1] = fast_tanh(red8(pr2 + 80) + bA1_1);
#pragma unroll
        for (int ib = 0; ib < 4; ib++) xc[ib] = xn[ib];
        GBAR(grp);
        cur = nxt;
    }
    // T_LEN even -> final h2 is in h2[0]
    __syncthreads();

    // ---------- FC head ----------
    {
        const int j = tid & 63;
        const int brow = tid >> 6;      // 0..3
#pragma unroll
        for (int rep = 0; rep < 2; rep++) {
            const int b = brow + rep * 4;
            float acc = bfc1[j];
#pragma unroll
            for (int c = 0; c < 8; c++) {
                const float* hb = &s->h2[0][b][c * 12];
                const float* wr = &Wfc1[j * H + c * 8];
#pragma unroll
                for (int u = 0; u < 8; u++) acc = fmaf(hb[u], wr[u], acc);
            }
            s->zfc[b][j] = fmaxf(acc, 0.f);
        }
    }
    __syncthreads();
    {
        const int b = tid >> 5;
        const int o = tid & 31;
        float r = bfc2[o];
#pragma unroll
        for (int k = 0; k < H; k++) r = fmaf(s->zfc[b][k], Wfc2[o * H + k], r);
        out[(blockIdx.x * BPB + b) * OUTF + o] = r;
    }
}

extern "C" void kernel_launch(void* const* d_in, const int* in_sizes, int n_in,
                              void* d_out, int out_size)
{
    (void)in_sizes; (void)n_in; (void)out_size;
    const float* x    = (const float*)d_in[0];
    const float* Wih1 = (const float*)d_in[1];
    const float* Whh1 = (const float*)d_in[2];
    const float* bih1 = (const float*)d_in[3];
    const float* bhh1 = (const float*)d_in[4];
    const float* Wih2 = (const float*)d_in[5];
    const float* Whh2 = (const float*)d_in[6];
    const float* bih2 = (const float*)d_in[7];
    const float* bhh2 = (const float*)d_in[8];
    const float* Wfc1 = (const float*)d_in[9];
    const float* bfc1 = (const float*)d_in[10];
    const float* Wfc2 = (const float*)d_in[11];
    const float* bfc2 = (const float*)d_in[12];
    float* out = (float*)d_out;

    size_t smem = sizeof(Smem);
    cudaFuncSetAttribute(rnn_fused_kernel,
                         cudaFuncAttributeMaxDynamicSharedMemorySize, (int)smem);
    rnn_fused_kernel<<<NBLK, NTHR, smem>>>(x, Wih1, Whh1, bih1, bhh1,
                                           Wih2, Whh2, bih2, bhh2,
                                           Wfc1, bfc1, Wfc2, bfc2, out);
}

// round 8
// speedup vs baseline: 1.6217x; 1.1266x over previous
#include <cuda_runtime.h>

#define T_LEN 512
#define INF   32
#define H     64
#define OUTF  32
#define BPB   8
#define NBLK  128
#define NTHR  256             // 8 warps: warps 0-3 = group 0, 4-7 = group 1
#define SH    80              // plain h row stride (floats), bank-clean

typedef unsigned long long ull;

struct __align__(16) Smem {
    float h1[2][BPB][SH];
    float h2[2][BPB][SH];
    float zfc[BPB][H];
};

#define GBAR(g) asm volatile("bar.sync %0, 128;" :: "r"((g) + 1) : "memory")

__device__ __forceinline__ void fma2(ull& acc, ull a, ull b) {
    asm("fma.rn.f32x2 %0, %1, %2, %3;" : "=l"(acc) : "l"(a), "l"(b), "l"(acc));
}
__device__ __forceinline__ float foldA(ull v) {
    float2 f; asm("mov.b64 {%0, %1}, %2;" : "=f"(f.x), "=f"(f.y) : "l"(v));
    return f.x + f.y;
}
__device__ __forceinline__ float fast_tanh(float x) {
    float cx = fminf(fmaxf(x, -15.f), 15.f);
    float e;
    asm("ex2.approx.f32 %0, %1;" : "=f"(e) : "f"(cx * 2.8853900817779268f));
    float r;
    asm("rcp.approx.f32 %0, %1;" : "=f"(r) : "f"(e + 1.f));
    return (e - 1.f) * r;
}

// Reduce-scatter r[16] (v = ib*4 + jj) over 8 lanes (kg = lane&7).
// Lane kg returns final sums for v = 2kg and 2kg+1.
__device__ __forceinline__ float2 rscat(const float* r, bool b4, bool b2, bool b1) {
    float t8[8];
#pragma unroll
    for (int i = 0; i < 8; i++) {
        float snd = b4 ? r[i] : r[8 + i];
        float rec = __shfl_xor_sync(0xffffffffu, snd, 4);
        t8[i] = (b4 ? r[8 + i] : r[i]) + rec;
    }
    float t4[4];
#pragma unroll
    for (int i = 0; i < 4; i++) {
        float snd = b2 ? t8[i] : t8[4 + i];
        float rec = __shfl_xor_sync(0xffffffffu, snd, 2);
        t4[i] = (b2 ? t8[4 + i] : t8[i]) + rec;
    }
    float s0, s1;
    {
        float snd = b1 ? t4[0] : t4[2];
        float rec = __shfl_xor_sync(0xffffffffu, snd, 1);
        s0 = (b1 ? t4[2] : t4[0]) + rec;
        float snd2 = b1 ? t4[1] : t4[3];
        float rec2 = __shfl_xor_sync(0xffffffffu, snd2, 1);
        s1 = (b1 ? t4[3] : t4[1]) + rec2;
    }
    return make_float2(s0, s1);
}

__global__ void __launch_bounds__(NTHR, 1)
rnn_fused_kernel(const float* __restrict__ x,
                 const float* __restrict__ Wih1, const float* __restrict__ Whh1,
                 const float* __restrict__ bih1, const float* __restrict__ bhh1,
                 const float* __restrict__ Wih2, const float* __restrict__ Whh2,
                 const float* __restrict__ bih2, const float* __restrict__ bhh2,
                 const float* __restrict__ Wfc1, const float* __restrict__ bfc1,
                 const float* __restrict__ Wfc2, const float* __restrict__ bfc2,
                 float* __restrict__ out)
{
    __shared__ Smem s;
    const int tid  = threadIdx.x;
    const int lane = tid & 31;
    const int wrp  = tid >> 5;
    const int grp  = wrp >> 2;          // independent group 0/1
    const int wig  = wrp & 3;
    const int kg   = lane & 7;          // k-slice
    const int jgl  = lane >> 3;         // j-subgroup
    const int j4   = wig * 16 + jgl * 4;
    const int bq   = grp * 4;
    const int kx0  = kg * 4;
    const int kh0  = kg * 8;
    const bool b4 = kg & 4, b2 = kg & 2, b1 = kg & 1;

    // ---- weights into registers (k-paired for f32x2) ----
    ull w1[4][2], wh1[4][4], w2r[4][4], wh2[4][4];
#pragma unroll
    for (int u = 0; u < 4; u++) {
        ulonglong2 a = *(const ulonglong2*)&Wih1[(j4 + u) * INF + kx0];
        w1[u][0] = a.x; w1[u][1] = a.y;
        ulonglong2 c0 = *(const ulonglong2*)&Whh1[(j4 + u) * H + kh0];
        ulonglong2 c1 = *(const ulonglong2*)&Whh1[(j4 + u) * H + kh0 + 4];
        wh1[u][0] = c0.x; wh1[u][1] = c0.y; wh1[u][2] = c1.x; wh1[u][3] = c1.y;
        ulonglong2 d0 = *(const ulonglong2*)&Wih2[(j4 + u) * H + kh0];
        ulonglong2 d1 = *(const ulonglong2*)&Wih2[(j4 + u) * H + kh0 + 4];
        w2r[u][0] = d0.x; w2r[u][1] = d0.y; w2r[u][2] = d1.x; w2r[u][3] = d1.y;
        ulonglong2 e0 = *(const ulonglong2*)&Whh2[(j4 + u) * H + kh0];
        ulonglong2 e1 = *(const ulonglong2*)&Whh2[(j4 + u) * H + kh0 + 4];
        wh2[u][0] = e0.x; wh2[u][1] = e0.y; wh2[u][2] = e1.x; wh2[u][3] = e1.y;
    }

    // reduce-scatter output mapping: lane -> (bB, jB) and (bB, jB+1)
    const int bB = bq + (kg >> 1);
    const int jB = wig * 16 + jgl * 4 + 2 * (kg & 1);
    const float bA1x = bih1[jB] + bhh1[jB];
    const float bA1y = bih1[jB + 1] + bhh1[jB + 1];
    const float bA2x = bih2[jB] + bhh2[jB];
    const float bA2y = bih2[jB + 1] + bhh2[jB + 1];

    const float* xp0 = x + (size_t)(blockIdx.x * BPB + bq) * T_LEN * INF + kx0;

    // zero h state
    for (int i = tid; i < 2 * BPB * SH; i += NTHR) {
        (&s.h1[0][0][0])[i] = 0.f;
        (&s.h2[0][0][0])[i] = 0.f;
    }
    ulonglong2 xc[4], xn[4];
#pragma unroll
    for (int ib = 0; ib < 4; ib++)
        xc[ib] = *(const ulonglong2*)(xp0 + (size_t)ib * T_LEN * INF);
    __syncthreads();

    // ---------- preamble: h1(0) = tanh(x(0)@W1^T + b1) ----------
    {
        float rL[16];
#pragma unroll
        for (int ib = 0; ib < 4; ib++) {
            ull c0 = 0ull, c1 = 0ull, c2 = 0ull, c3 = 0ull;
            const ull xa = xc[ib].x, xb = xc[ib].y;
            fma2(c0, xa, w1[0][0]); fma2(c1, xa, w1[1][0]);
            fma2(c2, xa, w1[2][0]); fma2(c3, xa, w1[3][0]);
            fma2(c0, xb, w1[0][1]); fma2(c1, xb, w1[1][1]);
            fma2(c2, xb, w1[2][1]); fma2(c3, xb, w1[3][1]);
            rL[ib * 4 + 0] = foldA(c0); rL[ib * 4 + 1] = foldA(c1);
            rL[ib * 4 + 2] = foldA(c2); rL[ib * 4 + 3] = foldA(c3);
        }
        float2 v = rscat(rL, b4, b2, b1);
        *(float2*)&s.h1[1][bB][jB] =
            make_float2(fast_tanh(v.x + bA1x), fast_tanh(v.y + bA1y));
    }
#pragma unroll
    for (int ib = 0; ib < 4; ib++)
        xc[ib] = *(const ulonglong2*)(xp0 + (size_t)ib * T_LEN * INF + INF);  // x(1)
    GBAR(grp);

    // ---------- main loop: one group-local barrier per step ----------
    int cur = 0;
    for (int t = 0; t < T_LEN; t++) {
        const int nxt = cur ^ 1;
        const int tn = (t + 2 < T_LEN) ? (t + 2) : (T_LEN - 1);
#pragma unroll
        for (int ib = 0; ib < 4; ib++)
            xn[ib] = *(const ulonglong2*)(xp0 + (size_t)ib * T_LEN * INF + (size_t)tn * INF);

        float rL2[16], rL1[16];
#pragma unroll
        for (int ib = 0; ib < 4; ib++) {
            const float* hb1 = &s.h1[nxt][bq + ib][kh0];   // h1(t)
            const float* hb2 = &s.h2[cur][bq + ib][kh0];   // h2(t-1)
            ulonglong2 p0 = *(const ulonglong2*)hb1;
            ulonglong2 p1 = *(const ulonglong2*)(hb1 + 4);
            ulonglong2 q0 = *(const ulonglong2*)hb2;
            ulonglong2 q1 = *(const ulonglong2*)(hb2 + 4);

            // layer2(t): h1(t)@W2^T + h2(t-1)@Wh2^T
            ull a0 = 0ull, a1 = 0ull, a2 = 0ull, a3 = 0ull;
            fma2(a0, p0.x, w2r[0][0]); fma2(a1, p0.x, w2r[1][0]);
            fma2(a2, p0.x, w2r[2][0]); fma2(a3, p0.x, w2r[3][0]);
            fma2(a0, p0.y, w2r[0][1]); fma2(a1, p0.y, w2r[1][1]);
            fma2(a2, p0.y, w2r[2][1]); fma2(a3, p0.y, w2r[3][1]);
            fma2(a0, p1.x, w2r[0][2]); fma2(a1, p1.x, w2r[1][2]);
            fma2(a2, p1.x, w2r[2][2]); fma2(a3, p1.x, w2r[3][2]);
            fma2(a0, p1.y, w2r[0][3]); fma2(a1, p1.y, w2r[1][3]);
            fma2(a2, p1.y, w2r[2][3]); fma2(a3, p1.y, w2r[3][3]);
            fma2(a0, q0.x, wh2[0][0]); fma2(a1, q0.x, wh2[1][0]);
            fma2(a2, q0.x, wh2[2][0]); fma2(a3, q0.x, wh2[3][0]);
            fma2(a0, q0.y, wh2[0][1]); fma2(a1, q0.y, wh2[1][1]);
            fma2(a2, q0.y, wh2[2][1]); fma2(a3, q0.y, wh2[3][1]);
            fma2(a0, q1.x, wh2[0][2]); fma2(a1, q1.x, wh2[1][2]);
            fma2(a2, q1.x, wh2[2][2]); fma2(a3, q1.x, wh2[3][2]);
            fma2(a0, q1.y, wh2[0][3]); fma2(a1, q1.y, wh2[1][3]);
            fma2(a2, q1.y, wh2[2][3]); fma2(a3, q1.y, wh2[3][3]);
            rL2[ib * 4 + 0] = foldA(a0); rL2[ib * 4 + 1] = foldA(a1);
            rL2[ib * 4 + 2] = foldA(a2); rL2[ib * 4 + 3] = foldA(a3);

            // layer1(t+1): x(t+1)@W1^T + h1(t)@Wh1^T   (reuses p0/p1)
            ull c0 = 0ull, c1 = 0ull, c2 = 0ull, c3 = 0ull;
            const ull xa = xc[ib].x, xb = xc[ib].y;
            fma2(c0, xa, w1[0][0]); fma2(c1, xa, w1[1][0]);
            fma2(c2, xa, w1[2][0]); fma2(c3, xa, w1[3][0]);
            fma2(c0, xb, w1[0][1]); fma2(c1, xb, w1[1][1]);
            fma2(c2, xb, w1[2][1]); fma2(c3, xb, w1[3][1]);
            fma2(c0, p0.x, wh1[0][0]); fma2(c1, p0.x, wh1[1][0]);
            fma2(c2, p0.x, wh1[2][0]); fma2(c3, p0.x, wh1[3][0]);
            fma2(c0, p0.y, wh1[0][1]); fma2(c1, p0.y, wh1[1][1]);
            fma2(c2, p0.y, wh1[2][1]); fma2(c3, p0.y, wh1[3][1]);
            fma2(c0, p1.x, wh1[0][2]); fma2(c1, p1.x, wh1[1][2]);
            fma2(c2, p1.x, wh1[2][2]); fma2(c3, p1.x, wh1[3][2]);
            fma2(c0, p1.y, wh1[0][3]); fma2(c1, p1.y, wh1[1][3]);
            fma2(c2, p1.y, wh1[2][3]); fma2(c3, p1.y, wh1[3][3]);
            rL1[ib * 4 + 0] = foldA(c0); rL1[ib * 4 + 1] = foldA(c1);
            rL1[ib * 4 + 2] = foldA(c2); rL1[ib * 4 + 3] = foldA(c3);
        }

        // shuffle reduce-scatter + tanh + store (no smem partials)
        float2 v2 = rscat(rL2, b4, b2, b1);
        *(float2*)&s.h2[nxt][bB][jB] =
            make_float2(fast_tanh(v2.x + bA2x), fast_tanh(v2.y + bA2y));
        float2 v1 = rscat(rL1, b4, b2, b1);
        *(float2*)&s.h1[cur][bB][jB] =
            make_float2(fast_tanh(v1.x + bA1x), fast_tanh(v1.y + bA1y));

#pragma unroll
        for (int ib = 0; ib < 4; ib++) xc[ib] = xn[ib];
        GBAR(grp);
        cur = nxt;
    }
    // T_LEN even -> final h2 is in h2[0]
    __syncthreads();

    // ---------- FC head ----------
    {
        const int j = tid & 63;
        const int brow = tid >> 6;      // 0..3
#pragma unroll
        for (int rep = 0; rep < 2; rep++) {
            const int b = brow + rep * 4;
            float acc = bfc1[j];
            const float* hb = &s.h2[0][b][0];
            const float* wr = &Wfc1[j * H];
#pragma unroll
            for (int k = 0; k < H; k += 4) {
                float4 hv = *(const float4*)(hb + k);
                float4 wv = *(const float4*)(wr + k);
                acc = fmaf(hv.x, wv.x, acc); acc = fmaf(hv.y, wv.y, acc);
                acc = fmaf(hv.z, wv.z, acc); acc = fmaf(hv.w, wv.w, acc);
            }
            s.zfc[b][j] = fmaxf(acc, 0.f);
        }
    }
    __syncthreads();
    {
        const int b = tid >> 5;
        const int o = tid & 31;
        float r = bfc2[o];
#pragma unroll
        for (int k = 0; k < H; k += 4) {
            float4 zv = *(const float4*)&s.zfc[b][k];
            float4 wv = *(const float4*)&Wfc2[o * H + k];
            r = fmaf(zv.x, wv.x, r); r = fmaf(zv.y, wv.y, r);
            r = fmaf(zv.z, wv.z, r); r = fmaf(zv.w, wv.w, r);
        }
        out[(blockIdx.x * BPB + b) * OUTF + o] = r;
    }
}

extern "C" void kernel_launch(void* const* d_in, const int* in_sizes, int n_in,
                              void* d_out, int out_size)
{
    (void)in_sizes; (void)n_in; (void)out_size;
    const float* x    = (const float*)d_in[0];
    const float* Wih1 = (const float*)d_in[1];
    const float* Whh1 = (const float*)d_in[2];
    const float* bih1 = (const float*)d_in[3];
    const float* bhh1 = (const float*)d_in[4];
    const float* Wih2 = (const float*)d_in[5];
    const float* Whh2 = (const float*)d_in[6];
    const float* bih2 = (const float*)d_in[7];
    const float* bhh2 = (const float*)d_in[8];
    const float* Wfc1 = (const float*)d_in[9];
    const float* bfc1 = (const float*)d_in[10];
    const float* Wfc2 = (const float*)d_in[11];
    const float* bfc2 = (const float*)d_in[12];
    float* out = (float*)d_out;

    rnn_fused_kernel<<<NBLK, NTHR>>>(x, Wih1, Whh1, bih1, bhh1,
                                     Wih2, Whh2, bih2, bhh2,
                                     Wfc1, bfc1, Wfc2, bfc2, out);
}

// round 9
// speedup vs baseline: 1.9297x; 1.1899x over previous
#include <cuda_runtime.h>

#define T_LEN 512
#define INF   32
#define H     64
#define OUTF  32
#define BPB   8
#define NBLK  128
#define NTHR  256             // 8 warps: warps 0-3 = group 0, 4-7 = group 1
#define SH    96              // h row stride; element j at (j>>3)*12 + (j&7)

typedef unsigned long long ull;

#define GBAR(g) asm volatile("bar.sync %0, 128;" :: "r"((g) + 1) : "memory")

__device__ __forceinline__ void fma2(ull& acc, ull a, ull b) {
    asm("fma.rn.f32x2 %0, %1, %2, %3;" : "=l"(acc) : "l"(a), "l"(b), "l"(acc));
}
__device__ __forceinline__ float foldA(ull v) {
    float2 f; asm("mov.b64 {%0, %1}, %2;" : "=f"(f.x), "=f"(f.y) : "l"(v));
    return f.x + f.y;
}
__device__ __forceinline__ float fast_tanh(float x) {
    float cx = fminf(fmaxf(x, -15.f), 15.f);
    float e;
    asm("ex2.approx.f32 %0, %1;" : "=f"(e) : "f"(cx * 2.8853900817779268f));
    float r;
    asm("rcp.approx.f32 %0, %1;" : "=f"(r) : "f"(e + 1.f));
    return (e - 1.f) * r;
}

// No-select reduce-scatter: slot meanings are lane-permuted (bit-XORed with kg)
// so every stage is keep-low-half / send-high-half.
__device__ __forceinline__ float2 rscat(const float* r) {
    float t8[8];
#pragma unroll
    for (int i = 0; i < 8; i++)
        t8[i] = r[i] + __shfl_xor_sync(0xffffffffu, r[8 + i], 4);
    float t4[4];
#pragma unroll
    for (int i = 0; i < 4; i++)
        t4[i] = t8[i] + __shfl_xor_sync(0xffffffffu, t8[4 + i], 2);
    float s0 = t4[0] + __shfl_xor_sync(0xffffffffu, t4[2], 1);
    float s1 = t4[1] + __shfl_xor_sync(0xffffffffu, t4[3], 1);
    return make_float2(s0, s1);
}

__global__ void __launch_bounds__(NTHR, 1)
rnn_fused_kernel(const float* __restrict__ x,
                 const float* __restrict__ Wih1, const float* __restrict__ Whh1,
                 const float* __restrict__ bih1, const float* __restrict__ bhh1,
                 const float* __restrict__ Wih2, const float* __restrict__ Whh2,
                 const float* __restrict__ bih2, const float* __restrict__ bhh2,
                 const float* __restrict__ Wfc1, const float* __restrict__ bfc1,
                 const float* __restrict__ Wfc2, const float* __restrict__ bfc2,
                 float* __restrict__ out)
{
    __shared__ float h1s[2][BPB][SH];
    __shared__ float h2s[2][BPB][SH];
    __shared__ float zfc[BPB][H];

    const int tid  = threadIdx.x;
    const int lane = tid & 31;
    const int wrp  = tid >> 5;
    const int grp  = wrp >> 2;          // independent group 0/1
    const int wig  = wrp & 3;
    const int kg   = lane & 7;          // k-slice
    const int jgl  = lane >> 3;         // j-subgroup
    const int j4   = wig * 16 + jgl * 4;
    const int bq   = grp * 4;
    const int kx0  = kg * 4;
    const int kh0  = kg * 8;
    const int bpx  = kg >> 1;           // batch-slot permutation
    const int jpx  = (kg & 1) << 1;     // j-slot permutation

    // ---- weights into registers, j-PERMUTED: acc u covers j = j4 + (u^jpx) ----
    ull w1[4][2], wh1[4][4], w2r[4][4], wh2[4][4];
#pragma unroll
    for (int u = 0; u < 4; u++) {
        const int ju = j4 + (u ^ jpx);
        ulonglong2 a = *(const ulonglong2*)&Wih1[ju * INF + kx0];
        w1[u][0] = a.x; w1[u][1] = a.y;
        ulonglong2 c0 = *(const ulonglong2*)&Whh1[ju * H + kh0];
        ulonglong2 c1 = *(const ulonglong2*)&Whh1[ju * H + kh0 + 4];
        wh1[u][0] = c0.x; wh1[u][1] = c0.y; wh1[u][2] = c1.x; wh1[u][3] = c1.y;
        ulonglong2 d0 = *(const ulonglong2*)&Wih2[ju * H + kh0];
        ulonglong2 d1 = *(const ulonglong2*)&Wih2[ju * H + kh0 + 4];
        w2r[u][0] = d0.x; w2r[u][1] = d0.y; w2r[u][2] = d1.x; w2r[u][3] = d1.y;
        ulonglong2 e0 = *(const ulonglong2*)&Whh2[ju * H + kh0];
        ulonglong2 e1 = *(const ulonglong2*)&Whh2[ju * H + kh0 + 4];
        wh2[u][0] = e0.x; wh2[u][1] = e0.y; wh2[u][2] = e1.x; wh2[u][3] = e1.y;
    }

    // final outputs of this lane: (bB, jB), (bB, jB+1)
    const int bB = bq + (kg >> 1);
    const int jB = wig * 16 + jgl * 4 + 2 * (kg & 1);
    const float bA1x = bih1[jB] + bhh1[jB];
    const float bA1y = bih1[jB + 1] + bhh1[jB + 1];
    const float bA2x = bih2[jB] + bhh2[jB];
    const float bA2y = bih2[jB + 1] + bhh2[jB + 1];
    const int hwB = bB * SH + (jB >> 3) * 12 + (jB & 7);   // store index (jB&7 even)

    // per-slot h row offsets (batch-permuted) and x pointers
    int hoff[4];
    const float* xq[4];
#pragma unroll
    for (int sb = 0; sb < 4; sb++) {
        const int ab = sb ^ bpx;
        hoff[sb] = (bq + ab) * SH + kg * 12;
        xq[sb] = x + (size_t)(blockIdx.x * BPB + bq + ab) * T_LEN * INF + kx0;
    }

    float* const h1b0 = &h1s[0][0][0];
    float* const h1b1 = &h1s[1][0][0];
    float* const h2b0 = &h2s[0][0][0];
    float* const h2b1 = &h2s[1][0][0];

    // zero h state
    for (int i = tid; i < 2 * BPB * SH; i += NTHR) {
        h1b0[i] = 0.f;   // covers h1s[0..1]
        h2b0[i] = 0.f;
    }
    ulonglong2 X0[4], X1[4];
#pragma unroll
    for (int sb = 0; sb < 4; sb++) X0[sb] = *(const ulonglong2*)(xq[sb]);
    __syncthreads();

    // ---------- preamble: h1(0) = tanh(x(0)@W1^T + b1) -> h1s[1] ----------
    {
        float rL[16];
#pragma unroll
        for (int sb = 0; sb < 4; sb++) {
            ull c0 = 0ull, c1 = 0ull, c2 = 0ull, c3 = 0ull;
            const ull xa = X0[sb].x, xb = X0[sb].y;
            fma2(c0, xa, w1[0][0]); fma2(c1, xa, w1[1][0]);
            fma2(c2, xa, w1[2][0]); fma2(c3, xa, w1[3][0]);
            fma2(c0, xb, w1[0][1]); fma2(c1, xb, w1[1][1]);
            fma2(c2, xb, w1[2][1]); fma2(c3, xb, w1[3][1]);
            rL[sb * 4 + 0] = foldA(c0); rL[sb * 4 + 1] = foldA(c1);
            rL[sb * 4 + 2] = foldA(c2); rL[sb * 4 + 3] = foldA(c3);
        }
        float2 v = rscat(rL);
        *(float2*)(h1b1 + hwB) =
            make_float2(fast_tanh(v.x + bA1x), fast_tanh(v.y + bA1y));
    }
#pragma unroll
    for (int sb = 0; sb < 4; sb++)
        X0[sb] = *(const ulonglong2*)(xq[sb] + INF);   // x(1)
    GBAR(grp);

// One timestep: reads h1(t)=H1R, h2(t-1)=H2R; writes h2(t)=H2W, h1(t+1)=H1W.
// Consumes XC = x(t+1), prefetches XN = x(TN).
#define STEP(H1R, H2R, H2W, H1W, XC, XN, TN)                                   \
    do {                                                                       \
        const int tn_ = (TN);                                                  \
        _Pragma("unroll")                                                      \
        for (int sb = 0; sb < 4; sb++)                                         \
            XN[sb] = *(const ulonglong2*)(xq[sb] + (size_t)tn_ * INF);         \
        float rL2[16], rL1[16];                                                \
        _Pragma("unroll")                                                      \
        for (int sb = 0; sb < 4; sb++) {                                       \
            const float* hb1 = (H1R) + hoff[sb];                               \
            const float* hb2 = (H2R) + hoff[sb];                               \
            ulonglong2 p0 = *(const ulonglong2*)hb1;                           \
            ulonglong2 p1 = *(const ulonglong2*)(hb1 + 4);                     \
            ulonglong2 q0 = *(const ulonglong2*)hb2;                           \
            ulonglong2 q1 = *(const ulonglong2*)(hb2 + 4);                     \
            ull a0 = 0ull, a1 = 0ull, a2 = 0ull, a3 = 0ull;                    \
            fma2(a0, p0.x, w2r[0][0]); fma2(a1, p0.x, w2r[1][0]);              \
            fma2(a2, p0.x, w2r[2][0]); fma2(a3, p0.x, w2r[3][0]);              \
            fma2(a0, p0.y, w2r[0][1]); fma2(a1, p0.y, w2r[1][1]);              \
            fma2(a2, p0.y, w2r[2][1]); fma2(a3, p0.y, w2r[3][1]);              \
            fma2(a0, p1.x, w2r[0][2]); fma2(a1, p1.x, w2r[1][2]);              \
            fma2(a2, p1.x, w2r[2][2]); fma2(a3, p1.x, w2r[3][2]);              \
            fma2(a0, p1.y, w2r[0][3]); fma2(a1, p1.y, w2r[1][3]);              \
            fma2(a2, p1.y, w2r[2][3]); fma2(a3, p1.y, w2r[3][3]);              \
            fma2(a0, q0.x, wh2[0][0]); fma2(a1, q0.x, wh2[1][0]);              \
            fma2(a2, q0.x, wh2[2][0]); fma2(a3, q0.x, wh2[3][0]);              \
            fma2(a0, q0.y, wh2[0][1]); fma2(a1, q0.y, wh2[1][1]);              \
            fma2(a2, q0.y, wh2[2][1]); fma2(a3, q0.y, wh2[3][1]);              \
            fma2(a0, q1.x, wh2[0][2]); fma2(a1, q1.x, wh2[1][2]);              \
            fma2(a2, q1.x, wh2[2][2]); fma2(a3, q1.x, wh2[3][2]);              \
            fma2(a0, q1.y, wh2[0][3]); fma2(a1, q1.y, wh2[1][3]);              \
            fma2(a2, q1.y, wh2[2][3]); fma2(a3, q1.y, wh2[3][3]);              \
            rL2[sb * 4 + 0] = foldA(a0); rL2[sb * 4 + 1] = foldA(a1);          \
            rL2[sb * 4 + 2] = foldA(a2); rL2[sb * 4 + 3] = foldA(a3);          \
            ull c0 = 0ull, c1 = 0ull, c2 = 0ull, c3 = 0ull;                    \
            const ull xa = XC[sb].x, xb = XC[sb].y;                            \
            fma2(c0, xa, w1[0][0]); fma2(c1, xa, w1[1][0]);                    \
            fma2(c2, xa, w1[2][0]); fma2(c3, xa, w1[3][0]);                    \
            fma2(c0, xb, w1[0][1]); fma2(c1, xb, w1[1][1]);                    \
            fma2(c2, xb, w1[2][1]); fma2(c3, xb, w1[3][1]);                    \
            fma2(c0, p0.x, wh1[0][0]); fma2(c1, p0.x, wh1[1][0]);              \
            fma2(c2, p0.x, wh1[2][0]); fma2(c3, p0.x, wh1[3][0]);              \
            fma2(c0, p0.y, wh1[0][1]); fma2(c1, p0.y, wh1[1][1]);              \
            fma2(c2, p0.y, wh1[2][1]); fma2(c3, p0.y, wh1[3][1]);              \
            fma2(c0, p1.x, wh1[0][2]); fma2(c1, p1.x, wh1[1][2]);              \
            fma2(c2, p1.x, wh1[2][2]); fma2(c3, p1.x, wh1[3][2]);              \
            fma2(c0, p1.y, wh1[0][3]); fma2(c1, p1.y, wh1[1][3]);              \
            fma2(c2, p1.y, wh1[2][3]); fma2(c3, p1.y, wh1[3][3]);              \
            rL1[sb * 4 + 0] = foldA(c0); rL1[sb * 4 + 1] = foldA(c1);          \
            rL1[sb * 4 + 2] = foldA(c2); rL1[sb * 4 + 3] = foldA(c3);          \
        }                                                                      \
        float2 v2 = rscat(rL2);                                                \
        *(float2*)((H2W) + hwB) =                                              \
            make_float2(fast_tanh(v2.x + bA2x), fast_tanh(v2.y + bA2y));       \
        float2 v1 = rscat(rL1);                                                \
        *(float2*)((H1W) + hwB) =                                              \
            make_float2(fast_tanh(v1.x + bA1x), fast_tanh(v1.y + bA1y));       \
        GBAR(grp);                                                             \
    } while (0)

    for (int t = 0; t < T_LEN; t += 2) {
        const int tnA = (t + 2 < T_LEN) ? t + 2 : T_LEN - 1;
        STEP(h1b1, h2b0, h2b1, h1b0, X0, X1, tnA);
        const int tnB = (t + 3 < T_LEN) ? t + 3 : T_LEN - 1;
        STEP(h1b0, h2b1, h2b0, h1b1, X1, X0, tnB);
    }
    // final h2(511) is in h2s[0]
    __syncthreads();

    // ---------- FC head ----------
    {
        const int j = tid & 63;
        const int brow = tid >> 6;      // 0..3
#pragma unroll
        for (int rep = 0; rep < 2; rep++) {
            const int b = brow + rep * 4;
            float acc = bfc1[j];
#pragma unroll
            for (int c = 0; c < 8; c++) {
                const float* hb = &h2s[0][b][c * 12];
                const float* wr = &Wfc1[j * H + c * 8];
#pragma unroll
                for (int u = 0; u < 8; u++) acc = fmaf(hb[u], wr[u], acc);
            }
            zfc[b][j] = fmaxf(acc, 0.f);
        }
    }
    __syncthreads();
    {
        const int b = tid >> 5;
        const int o = tid & 31;
        float r = bfc2[o];
#pragma unroll
        for (int k = 0; k < H; k += 4) {
            float4 zv = *(const float4*)&zfc[b][k];
            float4 wv = *(const float4*)&Wfc2[o * H + k];
            r = fmaf(zv.x, wv.x, r); r = fmaf(zv.y, wv.y, r);
            r = fmaf(zv.z, wv.z, r); r = fmaf(zv.w, wv.w, r);
        }
        out[(blockIdx.x * BPB + b) * OUTF + o] = r;
    }
}

extern "C" void kernel_launch(void* const* d_in, const int* in_sizes, int n_in,
                              void* d_out, int out_size)
{
    (void)in_sizes; (void)n_in; (void)out_size;
    const float* x    = (const float*)d_in[0];
    const float* Wih1 = (const float*)d_in[1];
    const float* Whh1 = (const float*)d_in[2];
    const float* bih1 = (const float*)d_in[3];
    const float* bhh1 = (const float*)d_in[4];
    const float* Wih2 = (const float*)d_in[5];
    const float* Whh2 = (const float*)d_in[6];
    const float* bih2 = (const float*)d_in[7];
    const float* bhh2 = (const float*)d_in[8];
    const float* Wfc1 = (const float*)d_in[9];
    const float* bfc1 = (const float*)d_in[10];
    const float* Wfc2 = (const float*)d_in[11];
    const float* bfc2 = (const float*)d_in[12];
    float* out = (float*)d_out;

    rnn_fused_kernel<<<NBLK, NTHR>>>(x, Wih1, Whh1, bih1, bhh1,
                                     Wih2, Whh2, bih2, bhh2,
                                     Wfc1, bfc1, Wfc2, bfc2, out);
}